// round 16
// baseline (speedup 1.0000x reference)
#include <cuda_runtime.h>
#include <cuda_fp16.h>
#include <math.h>

#define B 128
#define S 400
#define H 256
#define E 128
#define V 50000
#define OOV 50
#define TWOH 512
#define VO (V + OOV)

#define OFF_HT   (B * VO)
#define OFF_CT   (OFF_HT + B * H)
#define OFF_CTX  (OFF_CT + B * H)
#define OFF_AT   (OFF_CTX + B * TWOH)
#define OFF_GP   (OFF_AT + B * S)
#define OFF_COV  (OFF_GP + B)

__device__ float g_decbase[B * TWOH];
__device__ float g_et[B * S];
__device__ float g_hidden[B * H];
__device__ float g_logits[(size_t)B * V];   // holds exp(logit) after k4
__device__ float g_psum[B];
__device__ float g_ctxpart[B * 16 * TWOH];
__device__ float g_x[B * E];
__device__ float g_gates[B * 4 * H];
__device__ float g_status[B * TWOH];
__device__ unsigned g_WhHi[16 * 512 * 16];

__device__ __forceinline__ float sigf(float x) { return 1.0f / (1.0f + expf(-x)); }

__device__ __forceinline__ float fexp(float x) {
    float z = x * 1.4426950408889634f;
    z = fminf(fmaxf(z, -120.f), 120.f);
    float zm = z + 12582912.f;
    float n = zm - 12582912.f;
    int ni = __float_as_int(zm) - 0x4B400000;
    float f = z - n;
    float p = 1.5400517937e-4f;
    p = fmaf(p, f, 1.3333558146e-3f);
    p = fmaf(p, f, 9.6181291076e-3f);
    p = fmaf(p, f, 5.5504108665e-2f);
    p = fmaf(p, f, 2.4022650696e-1f);
    p = fmaf(p, f, 6.9314718056e-1f);
    p = fmaf(p, f, 1.0f);
    return p * __int_as_float((ni + 127) << 23);
}

__device__ __forceinline__ unsigned packhi(float x, float y) {
    __half hx = __float2half_rn(x), hy = __float2half_rn(y);
    return ((unsigned)__half_as_ushort(hy) << 16) | (unsigned)__half_as_ushort(hx);
}

__device__ __forceinline__ void mma16(float c[4], const unsigned a[4], unsigned b0, unsigned b1) {
    asm("mma.sync.aligned.m16n8k16.row.col.f32.f16.f16.f32 "
        "{%0,%1,%2,%3}, {%4,%5,%6,%7}, {%8,%9}, {%0,%1,%2,%3};"
        : "+f"(c[0]), "+f"(c[1]), "+f"(c[2]), "+f"(c[3])
        : "r"(a[0]), "r"(a[1]), "r"(a[2]), "r"(a[3]), "r"(b0), "r"(b1));
}

// ---------------------------------------------------------------------------
// k01: fused Wh-prepack (blocks 0..511) + x-projection GEMM (blocks 512..515).
// 256 thr. Independent work overlapped in one launch.
// ---------------------------------------------------------------------------
__global__ void k01_wh_x(
    const float* __restrict__ Wh,
    const int* __restrict__ idxv, const float* __restrict__ ctxv,
    const float* __restrict__ emb, const float* __restrict__ Wi,
    const float* __restrict__ bi)
{
    __shared__ __align__(16) float As[16][68];
    __shared__ __align__(16) float Ws[16][68];

    if (blockIdx.x < 512) {
        int idx = blockIdx.x * 256 + threadIdx.x;
        int n = idx >> 8;
        int kpg = idx & 255;
        int k = kpg * 2;
        int c = k >> 5, kp = (k & 31) >> 1;
        float2 v = *(const float2*)(Wh + (size_t)n * TWOH + k);
        g_WhHi[(c * 512 + n) * 16 + kp] = packhi(v.x, v.y);
        if (blockIdx.x == 0 && threadIdx.x < B) g_psum[threadIdx.x] = 0.f;
        return;
    }

    // x = Wi @ [ctx, emb] + bi.  M=128, N=128, K=640. 4 tile-blocks.
    const int blk = blockIdx.x - 512;
    const int m0 = (blk >> 1) * 64, n0 = (blk & 1) * 64;
    const int tid = threadIdx.x;
    const int tx = tid & 15, ty = tid >> 4;
    const int rl = tid >> 2, kq = tid & 3;

    float acc[4][4];
    #pragma unroll
    for (int a = 0; a < 4; a++)
        #pragma unroll
        for (int c = 0; c < 4; c++) acc[a][c] = 0.f;

    for (int kt = 0; kt < 40; kt++) {
        const int k = kt * 16 + kq * 4;
        const int m = m0 + rl;
        float4 av = (k < TWOH)
            ? *(const float4*)(ctxv + (size_t)m * TWOH + k)
            : *(const float4*)(emb + (size_t)idxv[m] * E + (k - TWOH));
        float4 wv = *(const float4*)(Wi + (size_t)(n0 + rl) * (TWOH + E) + k);
        __syncthreads();
        As[kq * 4 + 0][rl] = av.x; As[kq * 4 + 1][rl] = av.y;
        As[kq * 4 + 2][rl] = av.z; As[kq * 4 + 3][rl] = av.w;
        Ws[kq * 4 + 0][rl] = wv.x; Ws[kq * 4 + 1][rl] = wv.y;
        Ws[kq * 4 + 2][rl] = wv.z; Ws[kq * 4 + 3][rl] = wv.w;
        __syncthreads();
        #pragma unroll
        for (int kk = 0; kk < 16; kk++) {
            float ar[4], wr[4];
            *(float4*)ar = *(const float4*)&As[kk][ty * 4];
            *(float4*)wr = *(const float4*)&Ws[kk][tx * 4];
            #pragma unroll
            for (int mi = 0; mi < 4; mi++)
                #pragma unroll
                for (int jj = 0; jj < 4; jj++)
                    acc[mi][jj] += ar[mi] * wr[jj];
        }
    }
    #pragma unroll
    for (int mi = 0; mi < 4; mi++) {
        const int m = m0 + ty * 4 + mi;
        #pragma unroll
        for (int jj = 0; jj < 4; jj++) {
            const int o = n0 + tx * 4 + jj;
            g_x[m * E + o] = acc[mi][jj] + bi[o];
        }
    }
}

// ---------------------------------------------------------------------------
// k1b: gates = [x|h0] @ [W_ih|W_hh].T + biases. grid=(16,2).
// ---------------------------------------------------------------------------
__global__ void k1b_gates(
    const float* __restrict__ h0,
    const float* __restrict__ W_ih, const float* __restrict__ W_hh,
    const float* __restrict__ b_ih, const float* __restrict__ b_hh)
{
    __shared__ __align__(16) float As[16][68];
    __shared__ __align__(16) float Ws[16][68];
    const int tid = threadIdx.x;
    const int tx = tid & 15, ty = tid >> 4;
    const int rl = tid >> 2, kq = tid & 3;
    const int m0 = blockIdx.y * 64, n0 = blockIdx.x * 64;

    float acc[4][4];
    #pragma unroll
    for (int a = 0; a < 4; a++)
        #pragma unroll
        for (int c = 0; c < 4; c++) acc[a][c] = 0.f;

    for (int kt = 0; kt < 24; kt++) {
        const int k = kt * 16 + kq * 4;
        const int m = m0 + rl;
        const int n = n0 + rl;
        float4 av = (k < E)
            ? *(const float4*)(g_x + (size_t)m * E + k)
            : *(const float4*)(h0 + (size_t)m * H + (k - E));
        float4 wv = (k < E)
            ? *(const float4*)(W_ih + (size_t)n * E + k)
            : *(const float4*)(W_hh + (size_t)n * H + (k - E));
        __syncthreads();
        As[kq * 4 + 0][rl] = av.x; As[kq * 4 + 1][rl] = av.y;
        As[kq * 4 + 2][rl] = av.z; As[kq * 4 + 3][rl] = av.w;
        Ws[kq * 4 + 0][rl] = wv.x; Ws[kq * 4 + 1][rl] = wv.y;
        Ws[kq * 4 + 2][rl] = wv.z; Ws[kq * 4 + 3][rl] = wv.w;
        __syncthreads();
        #pragma unroll
        for (int kk = 0; kk < 16; kk++) {
            float ar[4], wr[4];
            *(float4*)ar = *(const float4*)&As[kk][ty * 4];
            *(float4*)wr = *(const float4*)&Ws[kk][tx * 4];
            #pragma unroll
            for (int mi = 0; mi < 4; mi++)
                #pragma unroll
                for (int jj = 0; jj < 4; jj++)
                    acc[mi][jj] += ar[mi] * wr[jj];
        }
    }
    #pragma unroll
    for (int mi = 0; mi < 4; mi++) {
        const int m = m0 + ty * 4 + mi;
        #pragma unroll
        for (int jj = 0; jj < 4; jj++) {
            const int o = n0 + tx * 4 + jj;
            g_gates[m * 4 * H + o] = acc[mi][jj] + b_ih[o] + b_hh[o];
        }
    }
}

// ---------------------------------------------------------------------------
// k1c: LSTM pointwise (per m-tile, into dynamic smem) + decbase GEMM.
// n0==0 blocks also write h_t/c_t/g_status. grid=(8,2), 256thr,
// dynamic smem 64*516*4 = 132096 B.
// ---------------------------------------------------------------------------
#define K1C_PITCH 516
#define K1C_SMEM (64 * K1C_PITCH * 4)

__global__ void k1c_decbase(
    const float* __restrict__ c0,
    const float* __restrict__ att_ws, const float* __restrict__ att_bc,
    float* __restrict__ out)
{
    extern __shared__ float sst[];   // [64][516] status tile
    __shared__ __align__(16) float As[16][68];
    __shared__ __align__(16) float Ws[16][68];
    const int tid = threadIdx.x;
    const int tx = tid & 15, ty = tid >> 4;
    const int rl = tid >> 2, kq = tid & 3;
    const int m0 = blockIdx.y * 64, n0 = blockIdx.x * 64;

    // LSTM pointwise for this block's 64 rows
    for (int i = tid; i < 64 * 256; i += 256) {
        const int r = i >> 8, j = i & 255;
        const int m = m0 + r;
        const float* gr = g_gates + (size_t)m * 4 * H;
        float ig = sigf(gr[j]);
        float fg = sigf(gr[H + j]);
        float gg = tanhf(gr[2 * H + j]);
        float og = sigf(gr[3 * H + j]);
        float c = fg * c0[m * H + j] + ig * gg;
        float h = og * tanhf(c);
        sst[r * K1C_PITCH + j] = h;
        sst[r * K1C_PITCH + 256 + j] = c;
        if (n0 == 0) {
            out[OFF_HT + m * H + j] = h;
            out[OFF_CT + m * H + j] = c;
            g_status[m * TWOH + j] = h;
            g_status[m * TWOH + 256 + j] = c;
        }
    }
    __syncthreads();

    float acc[4][4];
    #pragma unroll
    for (int a = 0; a < 4; a++)
        #pragma unroll
        for (int c = 0; c < 4; c++) acc[a][c] = 0.f;

    for (int kt = 0; kt < 32; kt++) {
        const int k = kt * 16 + kq * 4;
        float4 av = *(const float4*)(sst + rl * K1C_PITCH + k);
        float4 wv = *(const float4*)(att_ws + (size_t)(n0 + rl) * TWOH + k);
        __syncthreads();
        As[kq * 4 + 0][rl] = av.x; As[kq * 4 + 1][rl] = av.y;
        As[kq * 4 + 2][rl] = av.z; As[kq * 4 + 3][rl] = av.w;
        Ws[kq * 4 + 0][rl] = wv.x; Ws[kq * 4 + 1][rl] = wv.y;
        Ws[kq * 4 + 2][rl] = wv.z; Ws[kq * 4 + 3][rl] = wv.w;
        __syncthreads();
        #pragma unroll
        for (int kk = 0; kk < 16; kk++) {
            float ar[4], wr[4];
            *(float4*)ar = *(const float4*)&As[kk][ty * 4];
            *(float4*)wr = *(const float4*)&Ws[kk][tx * 4];
            #pragma unroll
            for (int mi = 0; mi < 4; mi++)
                #pragma unroll
                for (int jj = 0; jj < 4; jj++)
                    acc[mi][jj] += ar[mi] * wr[jj];
        }
    }
    #pragma unroll
    for (int mi = 0; mi < 4; mi++) {
        const int m = m0 + ty * 4 + mi;
        #pragma unroll
        for (int jj = 0; jj < 4; jj++) {
            const int o = n0 + tx * 4 + jj;
            g_decbase[m * TWOH + o] = acc[mi][jj] + att_bc[o];
        }
    }
}

// ---------------------------------------------------------------------------
// K2: attention scores, single-product fp16 mma, double-buffered (frozen).
// ---------------------------------------------------------------------------
#define K2P 20
#define K2_AH 0
#define K2_BH 5120
#define K2_BUF 46080
#define K2_SV  92160
#define K2_SWC 94208
#define K2_SDB 96256
#define K2_EP  100352
#define K2_SMEM 102400

__global__ void __launch_bounds__(512, 1) k2_mma(
    const float* __restrict__ EO,
    const float* __restrict__ att_wc, const float* __restrict__ att_v,
    const float* __restrict__ coverage, const int* __restrict__ mask)
{
    extern __shared__ char smem[];
    float* sv  = (float*)(smem + K2_SV);
    float* swc = (float*)(smem + K2_SWC);
    float* sdb = (float*)(smem + K2_SDB);
    float* ep  = (float*)(smem + K2_EP);

    const int tid = threadIdx.x;
    const int w = tid >> 5, lane = tid & 31;
    const int g = lane >> 2, t = lane & 3;
    const int wm = w & 1, wn = w >> 1;
    const int row0 = blockIdx.x * 64;
    const int b0 = row0 / S;
    const int b1e = (row0 + 63) / S;

    sv[tid] = att_v[tid];
    swc[tid] = att_wc[tid];
    sdb[tid] = g_decbase[b0 * TWOH + tid];
    sdb[512 + tid] = g_decbase[b1e * TWOH + tid];

    const int ar = tid >> 3, aq = tid & 7;
    const int bn = tid >> 2, bkq = tid & 3;
    const float* aptr = EO + (size_t)(row0 + ar) * TWOH + aq * 4;

    float c[2][8][4];
    #pragma unroll
    for (int mi = 0; mi < 2; mi++)
        #pragma unroll
        for (int ni = 0; ni < 8; ni++)
            #pragma unroll
            for (int q = 0; q < 4; q++) c[mi][ni][q] = 0.f;

    float4 av;
    uint4 bv[4];

    av = *(const float4*)(aptr);
    #pragma unroll
    for (int i = 0; i < 4; i++)
        bv[i] = *(const uint4*)(g_WhHi + ((size_t)(i * 128 + bn) * 16 + bkq * 4));
    {
        *(uint2*)((unsigned*)(smem + K2_AH) + ar * K2P + aq * 2) =
            make_uint2(packhi(av.x, av.y), packhi(av.z, av.w));
        unsigned* BHp = (unsigned*)(smem + K2_BH);
        #pragma unroll
        for (int i = 0; i < 4; i++)
            *(uint4*)(BHp + (i * 128 + bn) * K2P + bkq * 4) = bv[i];
    }
    __syncthreads();

    for (int kt = 0; kt < 16; kt++) {
        char* bufc = smem + (kt & 1) * K2_BUF;
        if (kt < 15) {
            av = *(const float4*)(aptr + (kt + 1) * 32);
            #pragma unroll
            for (int i = 0; i < 4; i++)
                bv[i] = *(const uint4*)(g_WhHi + ((size_t)((kt + 1) * 512 + i * 128 + bn) * 16 + bkq * 4));
        }

        unsigned* AHc = (unsigned*)(bufc + K2_AH);
        unsigned* BHc = (unsigned*)(bufc + K2_BH);
        #pragma unroll
        for (int s = 0; s < 2; s++) {
            unsigned ah[2][4];
            #pragma unroll
            for (int mi = 0; mi < 2; mi++) {
                const unsigned* pa = AHc + (wm * 32 + mi * 16 + g) * K2P + s * 8 + t;
                ah[mi][0] = pa[0]; ah[mi][1] = pa[8 * K2P];
                ah[mi][2] = pa[4]; ah[mi][3] = pa[8 * K2P + 4];
            }
            #pragma unroll
            for (int ni = 0; ni < 8; ni++) {
                const unsigned* pb = BHc + (wn * 64 + ni * 8 + g) * K2P + s * 8 + t;
                unsigned bh0 = pb[0], bh1 = pb[4];
                #pragma unroll
                for (int mi = 0; mi < 2; mi++)
                    mma16(c[mi][ni], ah[mi], bh0, bh1);
            }
        }

        if (kt < 15) {
            char* bufn = smem + ((kt + 1) & 1) * K2_BUF;
            *(uint2*)((unsigned*)(bufn + K2_AH) + ar * K2P + aq * 2) =
                make_uint2(packhi(av.x, av.y), packhi(av.z, av.w));
            unsigned* BHn = (unsigned*)(bufn + K2_BH);
            #pragma unroll
            for (int i = 0; i < 4; i++)
                *(uint4*)(BHn + (i * 128 + bn) * K2P + bkq * 4) = bv[i];
        }
        __syncthreads();
    }

    #pragma unroll
    for (int mi = 0; mi < 2; mi++) {
        #pragma unroll
        for (int hf = 0; hf < 2; hf++) {
            const int rl = wm * 32 + mi * 16 + hf * 8 + g;
            const int r = row0 + rl;
            const int dbo = (r / S != b0) ? 512 : 0;
            const float cov = coverage[r];
            float acc = 0.f;
            #pragma unroll
            for (int ni = 0; ni < 8; ni++) {
                const int j = wn * 64 + ni * 8 + t * 2;
                float v0 = c[mi][ni][hf * 2 + 0] + sdb[dbo + j] + cov * swc[j];
                float v1 = c[mi][ni][hf * 2 + 1] + sdb[dbo + j + 1] + cov * swc[j + 1];
                acc += sv[j] * tanhf(v0) + sv[j + 1] * tanhf(v1);
            }
            acc += __shfl_xor_sync(0xffffffffu, acc, 1);
            acc += __shfl_xor_sync(0xffffffffu, acc, 2);
            if (t == 0) ep[rl * 8 + wn] = acc;
        }
    }
    __syncthreads();
    if (tid < 64) {
        float sacc = 0.f;
        #pragma unroll
        for (int q = 0; q < 8; q++) sacc += ep[tid * 8 + q];
        const int r = row0 + tid;
        g_et[r] = (mask[r] == 0) ? -1e30f : sacc;
    }
}

// ---------------------------------------------------------------------------
__global__ void k3a_softmax(const float* __restrict__ coverage, float* __restrict__ out)
{
    const int b = blockIdx.x;
    const int t = threadIdx.x;
    __shared__ float red[512];

    float e = (t < S) ? g_et[b * S + t] : -1e30f;
    red[t] = e;
    __syncthreads();
    for (int off = 256; off > 0; off >>= 1) {
        if (t < off) red[t] = fmaxf(red[t], red[t + off]);
        __syncthreads();
    }
    const float mx = red[0];
    __syncthreads();

    float ex = (t < S) ? expf(e - mx) : 0.f;
    red[t] = ex;
    __syncthreads();
    for (int off = 256; off > 0; off >>= 1) {
        if (t < off) red[t] += red[t + off];
        __syncthreads();
    }
    const float inv = 1.f / red[0];

    if (t < S) {
        float a = ex * inv;
        out[OFF_AT + b * S + t] = a;
        out[OFF_COV + b * S + t] = coverage[b * S + t] + a;
    }
}

// ---------------------------------------------------------------------------
__global__ void k3c_ctxpart(const float* __restrict__ EO, const float* __restrict__ out)
{
    const int blk = blockIdx.x;
    const int b = blk >> 4, q = blk & 15;
    const int t = threadIdx.x;
    __shared__ float sa[25];
    if (t < 25) sa[t] = out[OFF_AT + b * S + q * 25 + t];
    __syncthreads();
    const float* eob = EO + ((size_t)b * S + q * 25) * TWOH;
    float c = 0.f;
    #pragma unroll 5
    for (int s = 0; s < 25; s++) c += sa[s] * eob[(size_t)s * TWOH + t];
    g_ctxpart[(size_t)blk * TWOH + t] = c;
}

// ---------------------------------------------------------------------------
// K3d: combine ctx partials + full gen_p (absorbed from old k1d). grid=(B), 512thr.
// ---------------------------------------------------------------------------
__global__ void k3d_ctx(
    const float* __restrict__ gp_wh,
    const float* __restrict__ gp_ws, const float* __restrict__ gp_bs,
    const float* __restrict__ gp_wx, const float* __restrict__ gp_bx,
    const float* __restrict__ gp_bh,
    float* __restrict__ out)
{
    const int b = blockIdx.x;
    const int t = threadIdx.x;
    __shared__ float red[512];
    float c = 0.f;
    #pragma unroll
    for (int q = 0; q < 16; q++)
        c += g_ctxpart[(size_t)(b * 16 + q) * TWOH + t];
    out[OFF_CTX + b * TWOH + t] = c;
    float p = gp_wh[t] * c + gp_ws[t] * g_status[b * TWOH + t];
    if (t < E) p += gp_wx[t] * g_x[b * E + t];
    red[t] = p;
    __syncthreads();
    for (int off = 256; off > 0; off >>= 1) {
        if (t < off) red[t] += red[t + off];
        __syncthreads();
    }
    if (t == 0) out[OFF_GP + b] = sigf(red[0] + gp_bs[0] + gp_bx[0] + gp_bh[0]);
}

// ---------------------------------------------------------------------------
__global__ void k3b_hidden(
    const float* __restrict__ out_w1, const float* __restrict__ out_b1,
    const float* __restrict__ out)
{
    __shared__ __align__(16) float As[16][68];
    __shared__ __align__(16) float Ws[16][68];

    const int tid = threadIdx.x;
    const int tx = tid & 15, ty = tid >> 4;
    const int rl = tid >> 2, kq = tid & 3;
    const int m0 = blockIdx.y * 64;
    const int n0 = blockIdx.x * 64;

    float acc[4][4];
    #pragma unroll
    for (int a = 0; a < 4; a++)
        #pragma unroll
        for (int c = 0; c < 4; c++) acc[a][c] = 0.f;

    for (int kt = 0; kt < 48; kt++) {
        const int k = kt * 16 + kq * 4;
        const int m = m0 + rl;
        float4 av = (k < H)
            ? *(const float4*)(out + OFF_HT + m * H + k)
            : *(const float4*)(out + OFF_CTX + m * TWOH + (k - H));
        float4 wv = *(const float4*)(out_w1 + (size_t)(n0 + rl) * (H + TWOH) + k);
        __syncthreads();
        As[kq * 4 + 0][rl] = av.x; As[kq * 4 + 1][rl] = av.y;
        As[kq * 4 + 2][rl] = av.z; As[kq * 4 + 3][rl] = av.w;
        Ws[kq * 4 + 0][rl] = wv.x; Ws[kq * 4 + 1][rl] = wv.y;
        Ws[kq * 4 + 2][rl] = wv.z; Ws[kq * 4 + 3][rl] = wv.w;
        __syncthreads();
        #pragma unroll
        for (int kk = 0; kk < 16; kk++) {
            float ar[4], wr[4];
            *(float4*)ar = *(const float4*)&As[kk][ty * 4];
            *(float4*)wr = *(const float4*)&Ws[kk][tx * 4];
            #pragma unroll
            for (int mi = 0; mi < 4; mi++)
                #pragma unroll
                for (int jj = 0; jj < 4; jj++)
                    acc[mi][jj] += ar[mi] * wr[jj];
        }
    }

    #pragma unroll
    for (int mi = 0; mi < 4; mi++) {
        const int m = m0 + ty * 4 + mi;
        #pragma unroll
        for (int jj = 0; jj < 4; jj++) {
            const int o = n0 + tx * 4 + jj;
            g_hidden[m * H + o] = fmaxf(acc[mi][jj] + out_b1[o], 0.f);
        }
    }
}

// ---------------------------------------------------------------------------
// K4: logits GEMM, single-product fp16 mma, 256n. Epilogue stores fexp(logit)
// + per-row psum. (frozen)
// ---------------------------------------------------------------------------
#define K4_AH 0
#define K4_BH 10240
#define K4_BUF 30720
#define K4_SMEM 61440

__global__ void __launch_bounds__(512, 1) k4_mma(
    const float* __restrict__ W2, const float* __restrict__ b2)
{
    extern __shared__ char smem[];

    const int tid = threadIdx.x;
    const int w = tid >> 5, lane = tid & 31;
    const int g = lane >> 2, t = lane & 3;
    const int wm = w & 3, wn = w >> 2;
    const int j0 = blockIdx.x * 256;

    const int ar = tid >> 3, aq = tid & 7;
    const int br = tid >> 3, bq = tid & 7;

    float c[2][8][4];
    #pragma unroll
    for (int mi = 0; mi < 2; mi++)
        #pragma unroll
        for (int ni = 0; ni < 8; ni++)
            #pragma unroll
            for (int q = 0; q < 4; q++) c[mi][ni][q] = 0.f;

    float4 avv[2], bvv[4];

    #pragma unroll
    for (int i = 0; i < 2; i++)
        avv[i] = *(const float4*)(g_hidden + (size_t)(i * 64 + ar) * H + aq * 4);
    #pragma unroll
    for (int i = 0; i < 4; i++) {
        int j = j0 + i * 64 + br;
        bvv[i] = (j < V) ? *(const float4*)(W2 + (size_t)j * H + bq * 4)
                         : make_float4(0.f, 0.f, 0.f, 0.f);
    }
    {
        unsigned* AHp = (unsigned*)(smem + K4_AH);
        unsigned* BHp = (unsigned*)(smem + K4_BH);
        #pragma unroll
        for (int i = 0; i < 2; i++)
            *(uint2*)(AHp + (i * 64 + ar) * K2P + aq * 2) =
                make_uint2(packhi(avv[i].x, avv[i].y), packhi(avv[i].z, avv[i].w));
        #pragma unroll
        for (int i = 0; i < 4; i++)
            *(uint2*)(BHp + (i * 64 + br) * K2P + bq * 2) =
                make_uint2(packhi(bvv[i].x, bvv[i].y), packhi(bvv[i].z, bvv[i].w));
    }
    __syncthreads();

    for (int kt = 0; kt < 8; kt++) {
        char* bufc = smem + (kt & 1) * K4_BUF;
        if (kt < 7) {
            const int k0 = (kt + 1) * 32;
            #pragma unroll
            for (int i = 0; i < 2; i++)
                avv[i] = *(const float4*)(g_hidden + (size_t)(i * 64 + ar) * H + k0 + aq * 4);
            #pragma unroll
            for (int i = 0; i < 4; i++) {
                int j = j0 + i * 64 + br;
                bvv[i] = (j < V) ? *(const float4*)(W2 + (size_t)j * H + k0 + bq * 4)
                                 : make_float4(0.f, 0.f, 0.f, 0.f);
            }
        }

        unsigned* AHc = (unsigned*)(bufc + K4_AH);
        unsigned* BHc = (unsigned*)(bufc + K4_BH);
        #pragma unroll
        for (int s = 0; s < 2; s++) {
            unsigned ah[2][4];
            #pragma unroll
            for (int mi = 0; mi < 2; mi++) {
                const unsigned* pa = AHc + (wm * 32 + mi * 16 + g) * K2P + s * 8 + t;
                ah[mi][0] = pa[0]; ah[mi][1] = pa[8 * K2P];
                ah[mi][2] = pa[4]; ah[mi][3] = pa[8 * K2P + 4];
            }
            #pragma unroll
            for (int ni = 0; ni < 8; ni++) {
                const unsigned* pb = BHc + (wn * 64 + ni * 8 + g) * K2P + s * 8 + t;
                unsigned bh0 = pb[0], bh1 = pb[4];
                #pragma unroll
                for (int mi = 0; mi < 2; mi++)
                    mma16(c[mi][ni], ah[mi], bh0, bh1);
            }
        }

        if (kt < 7) {
            char* bufn = smem + ((kt + 1) & 1) * K4_BUF;
            unsigned* AHn = (unsigned*)(bufn + K4_AH);
            unsigned* BHn = (unsigned*)(bufn + K4_BH);
            #pragma unroll
            for (int i = 0; i < 2; i++)
                *(uint2*)(AHn + (i * 64 + ar) * K2P + aq * 2) =
                    make_uint2(packhi(avv[i].x, avv[i].y), packhi(avv[i].z, avv[i].w));
            #pragma unroll
            for (int i = 0; i < 4; i++)
                *(uint2*)(BHn + (i * 64 + br) * K2P + bq * 2) =
                    make_uint2(packhi(bvv[i].x, bvv[i].y), packhi(bvv[i].z, bvv[i].w));
        }
        __syncthreads();
    }

    float* ssum = (float*)smem;
    #pragma unroll
    for (int mi = 0; mi < 2; mi++) {
        #pragma unroll
        for (int hf = 0; hf < 2; hf++) {
            const int r = wm * 32 + mi * 16 + hf * 8 + g;
            float ps = 0.f;
            #pragma unroll
            for (int ni = 0; ni < 8; ni++) {
                const int j = j0 + wn * 64 + ni * 8 + t * 2;
                if (j < V) {
                    float e0 = fexp(c[mi][ni][hf * 2 + 0] + b2[j]);
                    float e1 = fexp(c[mi][ni][hf * 2 + 1] + b2[j + 1]);
                    *(float2*)(g_logits + (size_t)r * V + j) = make_float2(e0, e1);
                    ps += e0 + e1;
                }
            }
            ps += __shfl_xor_sync(0xffffffffu, ps, 1);
            ps += __shfl_xor_sync(0xffffffffu, ps, 2);
            if (t == 0) ssum[r * 4 + wn] = ps;
        }
    }
    __syncthreads();
    if (tid < 128) {
        float s2 = ssum[tid * 4] + ssum[tid * 4 + 1] + ssum[tid * 4 + 2] + ssum[tid * 4 + 3];
        atomicAdd(&g_psum[tid], s2);
    }
}

// ---------------------------------------------------------------------------
__global__ void k5b_final(float* __restrict__ out)
{
    const int i = blockIdx.x * 256 + threadIdx.x;
    if (i >= B * VO) return;
    const int b = i / VO;
    const int c = i - b * VO;
    float v = 0.f;
    if (c < V) {
        const float gp = out[OFF_GP + b];
        v = g_logits[(size_t)b * V + c] * (1.f / g_psum[b]) * gp;
    }
    out[i] = v;
}

__global__ void k5c_scatter(const int* __restrict__ ewo, float* __restrict__ out)
{
    const int i = blockIdx.x * 256 + threadIdx.x;
    if (i >= B * S) return;
    const int b = i / S;
    const float gp = out[OFF_GP + b];
    const float a = out[OFF_AT + i];
    atomicAdd(out + (size_t)b * VO + ewo[i], a * (1.f - gp));
}

// ---------------------------------------------------------------------------
extern "C" void kernel_launch(void* const* d_in, const int* in_sizes, int n_in,
                              void* d_out, int out_size)
{
    const int*   idx      = (const int*)  d_in[0];
    const float* h0       = (const float*)d_in[1];
    const float* c0       = (const float*)d_in[2];
    const float* EO       = (const float*)d_in[3];
    const int*   emask    = (const int*)  d_in[4];
    const float* ctxv     = (const float*)d_in[5];
    const int*   ewo      = (const int*)  d_in[7];
    const float* coverage = (const float*)d_in[8];
    const float* emb      = (const float*)d_in[9];
    const float* Wi       = (const float*)d_in[10];
    const float* bi       = (const float*)d_in[11];
    const float* W_ih     = (const float*)d_in[12];
    const float* W_hh     = (const float*)d_in[13];
    const float* b_ih     = (const float*)d_in[14];
    const float* b_hh     = (const float*)d_in[15];
    const float* att_wh   = (const float*)d_in[16];
    const float* att_ws   = (const float*)d_in[17];
    const float* att_wc   = (const float*)d_in[18];
    const float* att_bc   = (const float*)d_in[19];
    const float* att_v    = (const float*)d_in[20];
    const float* gp_wh    = (const float*)d_in[21];
    const float* gp_bh    = (const float*)d_in[22];
    const float* gp_ws    = (const float*)d_in[23];
    const float* gp_bs    = (const float*)d_in[24];
    const float* gp_wx    = (const float*)d_in[25];
    const float* gp_bx    = (const float*)d_in[26];
    const float* out_w1   = (const float*)d_in[27];
    const float* out_b1   = (const float*)d_in[28];
    const float* out_w2   = (const float*)d_in[29];
    const float* out_b2   = (const float*)d_in[30];
    float* out = (float*)d_out;

    static int attr_done = 0;
    if (!attr_done) {
        cudaFuncSetAttribute(k2_mma, cudaFuncAttributeMaxDynamicSharedMemorySize, K2_SMEM);
        cudaFuncSetAttribute(k4_mma, cudaFuncAttributeMaxDynamicSharedMemorySize, K4_SMEM);
        cudaFuncSetAttribute(k1c_decbase, cudaFuncAttributeMaxDynamicSharedMemorySize, K1C_SMEM);
        attr_done = 1;
    }

    k01_wh_x<<<516, 256>>>(att_wh, idx, ctxv, emb, Wi, bi);
    {
        dim3 gb(16, 2);
        k1b_gates<<<gb, 256>>>(h0, W_ih, W_hh, b_ih, b_hh);
        dim3 gc(8, 2);
        k1c_decbase<<<gc, 256, K1C_SMEM>>>(c0, att_ws, att_bc, out);
    }
    k2_mma<<<(B * S) / 64, 512, K2_SMEM>>>(EO, att_wc, att_v, coverage, emask);
    k3a_softmax<<<B, 512>>>(coverage, out);
    k3c_ctxpart<<<B * 16, 512>>>(EO, out);
    k3d_ctx<<<B, 512>>>(gp_wh, gp_ws, gp_bs, gp_wx, gp_bx, gp_bh, out);
    {
        dim3 g3b(4, 2);
        k3b_hidden<<<g3b, 256>>>(out_w1, out_b1, out);
    }
    k4_mma<<<(V + 255) / 256, 512, K4_SMEM>>>(out_w2, out_b2);
    k5b_final<<<(B * VO + 255) / 256, 256>>>(out);
    k5c_scatter<<<(B * S + 255) / 256, 256>>>(ewo, out);
}

// round 17
// speedup vs baseline: 1.2841x; 1.2841x over previous
#include <cuda_runtime.h>
#include <cuda_fp16.h>
#include <math.h>

#define B 128
#define S 400
#define H 256
#define E 128
#define V 50000
#define OOV 50
#define TWOH 512
#define VO (V + OOV)

#define OFF_HT   (B * VO)
#define OFF_CT   (OFF_HT + B * H)
#define OFF_CTX  (OFF_CT + B * H)
#define OFF_AT   (OFF_CTX + B * TWOH)
#define OFF_GP   (OFF_AT + B * S)
#define OFF_COV  (OFF_GP + B)

__device__ float g_decbase[B * TWOH];
__device__ float g_gpart[B];
__device__ float g_et[B * S];
__device__ float g_hidden[B * H];
__device__ float g_logits[(size_t)B * V];   // holds exp(logit) after k4
__device__ float g_psum[B];
__device__ float g_ctxpart[B * 16 * TWOH];
__device__ float g_x[B * E];
__device__ float g_gates[B * 4 * H];
__device__ float g_status[B * TWOH];
__device__ unsigned g_WhHi[16 * 512 * 16];

__device__ __forceinline__ float sigf(float x) { return 1.0f / (1.0f + expf(-x)); }

__device__ __forceinline__ float fexp(float x) {
    float z = x * 1.4426950408889634f;
    z = fminf(fmaxf(z, -120.f), 120.f);
    float zm = z + 12582912.f;
    float n = zm - 12582912.f;
    int ni = __float_as_int(zm) - 0x4B400000;
    float f = z - n;
    float p = 1.5400517937e-4f;
    p = fmaf(p, f, 1.3333558146e-3f);
    p = fmaf(p, f, 9.6181291076e-3f);
    p = fmaf(p, f, 5.5504108665e-2f);
    p = fmaf(p, f, 2.4022650696e-1f);
    p = fmaf(p, f, 6.9314718056e-1f);
    p = fmaf(p, f, 1.0f);
    return p * __int_as_float((ni + 127) << 23);
}

__device__ __forceinline__ unsigned packhi(float x, float y) {
    __half hx = __float2half_rn(x), hy = __float2half_rn(y);
    return ((unsigned)__half_as_ushort(hy) << 16) | (unsigned)__half_as_ushort(hx);
}

__device__ __forceinline__ void mma16(float c[4], const unsigned a[4], unsigned b0, unsigned b1) {
    asm("mma.sync.aligned.m16n8k16.row.col.f32.f16.f16.f32 "
        "{%0,%1,%2,%3}, {%4,%5,%6,%7}, {%8,%9}, {%0,%1,%2,%3};"
        : "+f"(c[0]), "+f"(c[1]), "+f"(c[2]), "+f"(c[3])
        : "r"(a[0]), "r"(a[1]), "r"(a[2]), "r"(a[3]), "r"(b0), "r"(b1));
}

// ---------------------------------------------------------------------------
// K0: pre-pack Wh fp16 hi; zero g_psum + g_et. grid=(512), 256thr.
// ---------------------------------------------------------------------------
__global__ void k0_wh(const float* __restrict__ Wh)
{
    int idx = blockIdx.x * 256 + threadIdx.x;
    int n = idx >> 8;
    int kpg = idx & 255;
    int k = kpg * 2;
    int c = k >> 5, kp = (k & 31) >> 1;
    float2 v = *(const float2*)(Wh + (size_t)n * TWOH + k);
    g_WhHi[(c * 512 + n) * 16 + kp] = packhi(v.x, v.y);
    if (idx < B * S) g_et[idx] = 0.f;
    if (blockIdx.x == 0 && threadIdx.x < B) g_psum[threadIdx.x] = 0.f;
}

// ---------------------------------------------------------------------------
// k1a: x = Wi @ [ctx, emb] + bi. grid=(2,2), 256thr.
// ---------------------------------------------------------------------------
__global__ void k1a_x(
    const int* __restrict__ idxv, const float* __restrict__ ctxv,
    const float* __restrict__ emb, const float* __restrict__ Wi,
    const float* __restrict__ bi)
{
    __shared__ __align__(16) float As[16][68];
    __shared__ __align__(16) float Ws[16][68];
    const int tid = threadIdx.x;
    const int tx = tid & 15, ty = tid >> 4;
    const int rl = tid >> 2, kq = tid & 3;
    const int m0 = blockIdx.y * 64, n0 = blockIdx.x * 64;

    float acc[4][4];
    #pragma unroll
    for (int a = 0; a < 4; a++)
        #pragma unroll
        for (int c = 0; c < 4; c++) acc[a][c] = 0.f;

    for (int kt = 0; kt < 40; kt++) {
        const int k = kt * 16 + kq * 4;
        const int m = m0 + rl;
        float4 av = (k < TWOH)
            ? *(const float4*)(ctxv + (size_t)m * TWOH + k)
            : *(const float4*)(emb + (size_t)idxv[m] * E + (k - TWOH));
        float4 wv = *(const float4*)(Wi + (size_t)(n0 + rl) * (TWOH + E) + k);
        __syncthreads();
        As[kq * 4 + 0][rl] = av.x; As[kq * 4 + 1][rl] = av.y;
        As[kq * 4 + 2][rl] = av.z; As[kq * 4 + 3][rl] = av.w;
        Ws[kq * 4 + 0][rl] = wv.x; Ws[kq * 4 + 1][rl] = wv.y;
        Ws[kq * 4 + 2][rl] = wv.z; Ws[kq * 4 + 3][rl] = wv.w;
        __syncthreads();
        #pragma unroll
        for (int kk = 0; kk < 16; kk++) {
            float ar[4], wr[4];
            *(float4*)ar = *(const float4*)&As[kk][ty * 4];
            *(float4*)wr = *(const float4*)&Ws[kk][tx * 4];
            #pragma unroll
            for (int mi = 0; mi < 4; mi++)
                #pragma unroll
                for (int jj = 0; jj < 4; jj++)
                    acc[mi][jj] += ar[mi] * wr[jj];
        }
    }
    #pragma unroll
    for (int mi = 0; mi < 4; mi++) {
        const int m = m0 + ty * 4 + mi;
        #pragma unroll
        for (int jj = 0; jj < 4; jj++) {
            const int o = n0 + tx * 4 + jj;
            g_x[m * E + o] = acc[mi][jj] + bi[o];
        }
    }
}

// ---------------------------------------------------------------------------
// k1b: gates = [x|h0] @ [W_ih|W_hh].T + biases. grid=(16,2).
// ---------------------------------------------------------------------------
__global__ void k1b_gates(
    const float* __restrict__ h0,
    const float* __restrict__ W_ih, const float* __restrict__ W_hh,
    const float* __restrict__ b_ih, const float* __restrict__ b_hh)
{
    __shared__ __align__(16) float As[16][68];
    __shared__ __align__(16) float Ws[16][68];
    const int tid = threadIdx.x;
    const int tx = tid & 15, ty = tid >> 4;
    const int rl = tid >> 2, kq = tid & 3;
    const int m0 = blockIdx.y * 64, n0 = blockIdx.x * 64;

    float acc[4][4];
    #pragma unroll
    for (int a = 0; a < 4; a++)
        #pragma unroll
        for (int c = 0; c < 4; c++) acc[a][c] = 0.f;

    for (int kt = 0; kt < 24; kt++) {
        const int k = kt * 16 + kq * 4;
        const int m = m0 + rl;
        const int n = n0 + rl;
        float4 av = (k < E)
            ? *(const float4*)(g_x + (size_t)m * E + k)
            : *(const float4*)(h0 + (size_t)m * H + (k - E));
        float4 wv = (k < E)
            ? *(const float4*)(W_ih + (size_t)n * E + k)
            : *(const float4*)(W_hh + (size_t)n * H + (k - E));
        __syncthreads();
        As[kq * 4 + 0][rl] = av.x; As[kq * 4 + 1][rl] = av.y;
        As[kq * 4 + 2][rl] = av.z; As[kq * 4 + 3][rl] = av.w;
        Ws[kq * 4 + 0][rl] = wv.x; Ws[kq * 4 + 1][rl] = wv.y;
        Ws[kq * 4 + 2][rl] = wv.z; Ws[kq * 4 + 3][rl] = wv.w;
        __syncthreads();
        #pragma unroll
        for (int kk = 0; kk < 16; kk++) {
            float ar[4], wr[4];
            *(float4*)ar = *(const float4*)&As[kk][ty * 4];
            *(float4*)wr = *(const float4*)&Ws[kk][tx * 4];
            #pragma unroll
            for (int mi = 0; mi < 4; mi++)
                #pragma unroll
                for (int jj = 0; jj < 4; jj++)
                    acc[mi][jj] += ar[mi] * wr[jj];
        }
    }
    #pragma unroll
    for (int mi = 0; mi < 4; mi++) {
        const int m = m0 + ty * 4 + mi;
        #pragma unroll
        for (int jj = 0; jj < 4; jj++) {
            const int o = n0 + tx * 4 + jj;
            g_gates[m * 4 * H + o] = acc[mi][jj] + b_ih[o] + b_hh[o];
        }
    }
}

// ---------------------------------------------------------------------------
// k1b2: LSTM pointwise + gen_p partial. grid=(B), 256thr.
// ---------------------------------------------------------------------------
__global__ void k1b2_lstm(
    const float* __restrict__ c0, float* __restrict__ out,
    const float* __restrict__ gp_ws, const float* __restrict__ gp_bs,
    const float* __restrict__ gp_wx, const float* __restrict__ gp_bx,
    const float* __restrict__ gp_bh)
{
    const int b = blockIdx.x, t = threadIdx.x;
    __shared__ float red[256];
    const float* gr = g_gates + (size_t)b * 4 * H;
    float ig = sigf(gr[t]);
    float fg = sigf(gr[H + t]);
    float gg = tanhf(gr[2 * H + t]);
    float og = sigf(gr[3 * H + t]);
    float c = fg * c0[b * H + t] + ig * gg;
    float h = og * tanhf(c);
    out[OFF_HT + b * H + t] = h;
    out[OFF_CT + b * H + t] = c;
    g_status[b * TWOH + t] = h;
    g_status[b * TWOH + H + t] = c;

    float p = gp_ws[t] * h + gp_ws[256 + t] * c;
    if (t < E) p += gp_wx[t] * g_x[b * E + t];
    red[t] = p;
    __syncthreads();
    for (int off = 128; off > 0; off >>= 1) {
        if (t < off) red[t] += red[t + off];
        __syncthreads();
    }
    if (t == 0) g_gpart[b] = red[0] + gp_bs[0] + gp_bx[0] + gp_bh[0];
}

// ---------------------------------------------------------------------------
// k1c: decbase = status @ att_ws.T + att_bc. grid=(8,2).
// ---------------------------------------------------------------------------
__global__ void k1c_decbase(
    const float* __restrict__ att_ws, const float* __restrict__ att_bc)
{
    __shared__ __align__(16) float As[16][68];
    __shared__ __align__(16) float Ws[16][68];
    const int tid = threadIdx.x;
    const int tx = tid & 15, ty = tid >> 4;
    const int rl = tid >> 2, kq = tid & 3;
    const int m0 = blockIdx.y * 64, n0 = blockIdx.x * 64;

    float acc[4][4];
    #pragma unroll
    for (int a = 0; a < 4; a++)
        #pragma unroll
        for (int c = 0; c < 4; c++) acc[a][c] = 0.f;

    for (int kt = 0; kt < 32; kt++) {
        const int k = kt * 16 + kq * 4;
        float4 av = *(const float4*)(g_status + (size_t)(m0 + rl) * TWOH + k);
        float4 wv = *(const float4*)(att_ws + (size_t)(n0 + rl) * TWOH + k);
        __syncthreads();
        As[kq * 4 + 0][rl] = av.x; As[kq * 4 + 1][rl] = av.y;
        As[kq * 4 + 2][rl] = av.z; As[kq * 4 + 3][rl] = av.w;
        Ws[kq * 4 + 0][rl] = wv.x; Ws[kq * 4 + 1][rl] = wv.y;
        Ws[kq * 4 + 2][rl] = wv.z; Ws[kq * 4 + 3][rl] = wv.w;
        __syncthreads();
        #pragma unroll
        for (int kk = 0; kk < 16; kk++) {
            float ar[4], wr[4];
            *(float4*)ar = *(const float4*)&As[kk][ty * 4];
            *(float4*)wr = *(const float4*)&Ws[kk][tx * 4];
            #pragma unroll
            for (int mi = 0; mi < 4; mi++)
                #pragma unroll
                for (int jj = 0; jj < 4; jj++)
                    acc[mi][jj] += ar[mi] * wr[jj];
        }
    }
    #pragma unroll
    for (int mi = 0; mi < 4; mi++) {
        const int m = m0 + ty * 4 + mi;
        #pragma unroll
        for (int jj = 0; jj < 4; jj++) {
            const int o = n0 + tx * 4 + jj;
            g_decbase[m * TWOH + o] = acc[mi][jj] + att_bc[o];
        }
    }
}

// ---------------------------------------------------------------------------
// K2: attention scores, single-product fp16 mma, 256-thread CTAs for 2 CTA/SM.
// Block: 64 rows x 256 n (grid 800 x 2). 8 warps (2m x 4n), warp tile 32m x 64n.
// Epilogue atomicAdds e_t partials into g_et (zeroed by k0).
// ---------------------------------------------------------------------------
#define K2P 20
#define K2_AH 0
#define K2_BH 5120
#define K2_BUF 25600
#define K2_SV  51200
#define K2_SWC 52224
#define K2_SDB 53248
#define K2_EP  55296
#define K2_SMEM 56320

__global__ void __launch_bounds__(256, 2) k2_mma(
    const float* __restrict__ EO,
    const float* __restrict__ att_wc, const float* __restrict__ att_v,
    const float* __restrict__ coverage)
{
    extern __shared__ char smem[];
    float* sv  = (float*)(smem + K2_SV);    // [256]
    float* swc = (float*)(smem + K2_SWC);   // [256]
    float* sdb = (float*)(smem + K2_SDB);   // [2][256]
    float* ep  = (float*)(smem + K2_EP);    // [64][4]

    const int tid = threadIdx.x;
    const int w = tid >> 5, lane = tid & 31;
    const int g = lane >> 2, t = lane & 3;
    const int wm = w & 1, wn = w >> 1;      // 2m x 4n
    const int row0 = blockIdx.x * 64;
    const int nb = blockIdx.y * 256;
    const int b0 = row0 / S;
    const int b1e = (row0 + 63) / S;

    sv[tid] = att_v[nb + tid];
    swc[tid] = att_wc[nb + tid];
    sdb[tid] = g_decbase[b0 * TWOH + nb + tid];
    sdb[256 + tid] = g_decbase[b1e * TWOH + nb + tid];

    const int ar = tid >> 3, aq = tid & 7;      // A: rows i*32+ar (2 iters)
    const int bn = tid >> 2, bkq = tid & 3;     // B: n i*64+bn (4 iters)
    const float* aptr = EO + (size_t)(row0 + ar) * TWOH + aq * 4;

    float c[2][8][4];
    #pragma unroll
    for (int mi = 0; mi < 2; mi++)
        #pragma unroll
        for (int ni = 0; ni < 8; ni++)
            #pragma unroll
            for (int q = 0; q < 4; q++) c[mi][ni][q] = 0.f;

    float4 av[2];
    uint4 bv[4];

    // prologue chunk 0
    #pragma unroll
    for (int i = 0; i < 2; i++)
        av[i] = *(const float4*)(aptr + (size_t)i * 32 * TWOH);
    #pragma unroll
    for (int i = 0; i < 4; i++)
        bv[i] = *(const uint4*)(g_WhHi + ((size_t)(nb + i * 64 + bn) * 16 + bkq * 4));
    {
        unsigned* AHp = (unsigned*)(smem + K2_AH);
        unsigned* BHp = (unsigned*)(smem + K2_BH);
        #pragma unroll
        for (int i = 0; i < 2; i++)
            *(uint2*)(AHp + (i * 32 + ar) * K2P + aq * 2) =
                make_uint2(packhi(av[i].x, av[i].y), packhi(av[i].z, av[i].w));
        #pragma unroll
        for (int i = 0; i < 4; i++)
            *(uint4*)(BHp + (i * 64 + bn) * K2P + bkq * 4) = bv[i];
    }
    __syncthreads();

    for (int kt = 0; kt < 16; kt++) {
        char* bufc = smem + (kt & 1) * K2_BUF;
        if (kt < 15) {
            #pragma unroll
            for (int i = 0; i < 2; i++)
                av[i] = *(const float4*)(aptr + (size_t)i * 32 * TWOH + (kt + 1) * 32);
            #pragma unroll
            for (int i = 0; i < 4; i++)
                bv[i] = *(const uint4*)(g_WhHi +
                    ((size_t)((kt + 1) * 512 + nb + i * 64 + bn) * 16 + bkq * 4));
        }

        unsigned* AHc = (unsigned*)(bufc + K2_AH);
        unsigned* BHc = (unsigned*)(bufc + K2_BH);
        #pragma unroll
        for (int s = 0; s < 2; s++) {
            unsigned ah[2][4];
            #pragma unroll
            for (int mi = 0; mi < 2; mi++) {
                const unsigned* pa = AHc + (wm * 32 + mi * 16 + g) * K2P + s * 8 + t;
                ah[mi][0] = pa[0]; ah[mi][1] = pa[8 * K2P];
                ah[mi][2] = pa[4]; ah[mi][3] = pa[8 * K2P + 4];
            }
            #pragma unroll
            for (int ni = 0; ni < 8; ni++) {
                const unsigned* pb = BHc + (wn * 64 + ni * 8 + g) * K2P + s * 8 + t;
                unsigned bh0 = pb[0], bh1 = pb[4];
                #pragma unroll
                for (int mi = 0; mi < 2; mi++)
                    mma16(c[mi][ni], ah[mi], bh0, bh1);
            }
        }

        if (kt < 15) {
            char* bufn = smem + ((kt + 1) & 1) * K2_BUF;
            unsigned* AHn = (unsigned*)(bufn + K2_AH);
            unsigned* BHn = (unsigned*)(bufn + K2_BH);
            #pragma unroll
            for (int i = 0; i < 2; i++)
                *(uint2*)(AHn + (i * 32 + ar) * K2P + aq * 2) =
                    make_uint2(packhi(av[i].x, av[i].y), packhi(av[i].z, av[i].w));
            #pragma unroll
            for (int i = 0; i < 4; i++)
                *(uint4*)(BHn + (i * 64 + bn) * K2P + bkq * 4) = bv[i];
        }
        __syncthreads();
    }

    // epilogue: tanh + v-dot over this block's 256-n slice; atomicAdd partial
    #pragma unroll
    for (int mi = 0; mi < 2; mi++) {
        #pragma unroll
        for (int hf = 0; hf < 2; hf++) {
            const int rl = wm * 32 + mi * 16 + hf * 8 + g;
            const int r = row0 + rl;
            const int dbo = (r / S != b0) ? 256 : 0;
            const float cov = coverage[r];
            float acc = 0.f;
            #pragma unroll
            for (int ni = 0; ni < 8; ni++) {
                const int j = wn * 64 + ni * 8 + t * 2;
                float v0 = c[mi][ni][hf * 2 + 0] + sdb[dbo + j] + cov * swc[j];
                float v1 = c[mi][ni][hf * 2 + 1] + sdb[dbo + j + 1] + cov * swc[j + 1];
                acc += sv[j] * tanhf(v0) + sv[j + 1] * tanhf(v1);
            }
            acc += __shfl_xor_sync(0xffffffffu, acc, 1);
            acc += __shfl_xor_sync(0xffffffffu, acc, 2);
            if (t == 0) ep[rl * 4 + wn] = acc;
        }
    }
    __syncthreads();
    if (tid < 64) {
        float sacc = ep[tid * 4] + ep[tid * 4 + 1] + ep[tid * 4 + 2] + ep[tid * 4 + 3];
        atomicAdd(&g_et[row0 + tid], sacc);
    }
}

// ---------------------------------------------------------------------------
// K3a: masked softmax over S (mask applied here). grid=(B), 512thr.
// ---------------------------------------------------------------------------
__global__ void k3a_softmax(const float* __restrict__ coverage,
                            const int* __restrict__ emask, float* __restrict__ out)
{
    const int b = blockIdx.x;
    const int t = threadIdx.x;
    __shared__ float red[512];

    float e = -1e30f;
    if (t < S && emask[b * S + t] != 0) e = g_et[b * S + t];
    red[t] = e;
    __syncthreads();
    for (int off = 256; off > 0; off >>= 1) {
        if (t < off) red[t] = fmaxf(red[t], red[t + off]);
        __syncthreads();
    }
    const float mx = red[0];
    __syncthreads();

    float ex = (t < S) ? expf(e - mx) : 0.f;
    red[t] = ex;
    __syncthreads();
    for (int off = 256; off > 0; off >>= 1) {
        if (t < off) red[t] += red[t + off];
        __syncthreads();
    }
    const float inv = 1.f / red[0];

    if (t < S) {
        float a = ex * inv;
        out[OFF_AT + b * S + t] = a;
        out[OFF_COV + b * S + t] = coverage[b * S + t] + a;
    }
}

// ---------------------------------------------------------------------------
__global__ void k3c_ctxpart(const float* __restrict__ EO, const float* __restrict__ out)
{
    const int blk = blockIdx.x;
    const int b = blk >> 4, q = blk & 15;
    const int t = threadIdx.x;
    __shared__ float sa[25];
    if (t < 25) sa[t] = out[OFF_AT + b * S + q * 25 + t];
    __syncthreads();
    const float* eob = EO + ((size_t)b * S + q * 25) * TWOH;
    float c = 0.f;
    #pragma unroll 5
    for (int s = 0; s < 25; s++) c += sa[s] * eob[(size_t)s * TWOH + t];
    g_ctxpart[(size_t)blk * TWOH + t] = c;
}

// ---------------------------------------------------------------------------
__global__ void k3d_ctx(const float* __restrict__ gp_wh, float* __restrict__ out)
{
    const int b = blockIdx.x;
    const int t = threadIdx.x;
    __shared__ float red[512];
    float c = 0.f;
    #pragma unroll
    for (int q = 0; q < 16; q++)
        c += g_ctxpart[(size_t)(b * 16 + q) * TWOH + t];
    out[OFF_CTX + b * TWOH + t] = c;
    red[t] = gp_wh[t] * c;
    __syncthreads();
    for (int off = 256; off > 0; off >>= 1) {
        if (t < off) red[t] += red[t + off];
        __syncthreads();
    }
    if (t == 0) out[OFF_GP + b] = sigf(red[0] + g_gpart[b]);
}

// ---------------------------------------------------------------------------
__global__ void k3b_hidden(
    const float* __restrict__ out_w1, const float* __restrict__ out_b1,
    const float* __restrict__ out)
{
    __shared__ __align__(16) float As[16][68];
    __shared__ __align__(16) float Ws[16][68];

    const int tid = threadIdx.x;
    const int tx = tid & 15, ty = tid >> 4;
    const int rl = tid >> 2, kq = tid & 3;
    const int m0 = blockIdx.y * 64;
    const int n0 = blockIdx.x * 64;

    float acc[4][4];
    #pragma unroll
    for (int a = 0; a < 4; a++)
        #pragma unroll
        for (int c = 0; c < 4; c++) acc[a][c] = 0.f;

    for (int kt = 0; kt < 48; kt++) {
        const int k = kt * 16 + kq * 4;
        const int m = m0 + rl;
        float4 av = (k < H)
            ? *(const float4*)(out + OFF_HT + m * H + k)
            : *(const float4*)(out + OFF_CTX + m * TWOH + (k - H));
        float4 wv = *(const float4*)(out_w1 + (size_t)(n0 + rl) * (H + TWOH) + k);
        __syncthreads();
        As[kq * 4 + 0][rl] = av.x; As[kq * 4 + 1][rl] = av.y;
        As[kq * 4 + 2][rl] = av.z; As[kq * 4 + 3][rl] = av.w;
        Ws[kq * 4 + 0][rl] = wv.x; Ws[kq * 4 + 1][rl] = wv.y;
        Ws[kq * 4 + 2][rl] = wv.z; Ws[kq * 4 + 3][rl] = wv.w;
        __syncthreads();
        #pragma unroll
        for (int kk = 0; kk < 16; kk++) {
            float ar[4], wr[4];
            *(float4*)ar = *(const float4*)&As[kk][ty * 4];
            *(float4*)wr = *(const float4*)&Ws[kk][tx * 4];
            #pragma unroll
            for (int mi = 0; mi < 4; mi++)
                #pragma unroll
                for (int jj = 0; jj < 4; jj++)
                    acc[mi][jj] += ar[mi] * wr[jj];
        }
    }

    #pragma unroll
    for (int mi = 0; mi < 4; mi++) {
        const int m = m0 + ty * 4 + mi;
        #pragma unroll
        for (int jj = 0; jj < 4; jj++) {
            const int o = n0 + tx * 4 + jj;
            g_hidden[m * H + o] = fmaxf(acc[mi][jj] + out_b1[o], 0.f);
        }
    }
}

// ---------------------------------------------------------------------------
// K4: logits GEMM, single-product fp16 mma, 256n. Epilogue stores fexp(logit)
// + per-row psum. (frozen)
// ---------------------------------------------------------------------------
#define K4_AH 0
#define K4_BH 10240
#define K4_BUF 30720
#define K4_SMEM 61440

__global__ void __launch_bounds__(512, 1) k4_mma(
    const float* __restrict__ W2, const float* __restrict__ b2)
{
    extern __shared__ char smem[];

    const int tid = threadIdx.x;
    const int w = tid >> 5, lane = tid & 31;
    const int g = lane >> 2, t = lane & 3;
    const int wm = w & 3, wn = w >> 2;
    const int j0 = blockIdx.x * 256;

    const int ar = tid >> 3, aq = tid & 7;
    const int br = tid >> 3, bq = tid & 7;

    float c[2][8][4];
    #pragma unroll
    for (int mi = 0; mi < 2; mi++)
        #pragma unroll
        for (int ni = 0; ni < 8; ni++)
            #pragma unroll
            for (int q = 0; q < 4; q++) c[mi][ni][q] = 0.f;

    float4 avv[2], bvv[4];

    #pragma unroll
    for (int i = 0; i < 2; i++)
        avv[i] = *(const float4*)(g_hidden + (size_t)(i * 64 + ar) * H + aq * 4);
    #pragma unroll
    for (int i = 0; i < 4; i++) {
        int j = j0 + i * 64 + br;
        bvv[i] = (j < V) ? *(const float4*)(W2 + (size_t)j * H + bq * 4)
                         : make_float4(0.f, 0.f, 0.f, 0.f);
    }
    {
        unsigned* AHp = (unsigned*)(smem + K4_AH);
        unsigned* BHp = (unsigned*)(smem + K4_BH);
        #pragma unroll
        for (int i = 0; i < 2; i++)
            *(uint2*)(AHp + (i * 64 + ar) * K2P + aq * 2) =
                make_uint2(packhi(avv[i].x, avv[i].y), packhi(avv[i].z, avv[i].w));
        #pragma unroll
        for (int i = 0; i < 4; i++)
            *(uint2*)(BHp + (i * 64 + br) * K2P + bq * 2) =
                make_uint2(packhi(bvv[i].x, bvv[i].y), packhi(bvv[i].z, bvv[i].w));
    }
    __syncthreads();

    for (int kt = 0; kt < 8; kt++) {
        char* bufc = smem + (kt & 1) * K4_BUF;
        if (kt < 7) {
            const int k0 = (kt + 1) * 32;
            #pragma unroll
            for (int i = 0; i < 2; i++)
                avv[i] = *(const float4*)(g_hidden + (size_t)(i * 64 + ar) * H + k0 + aq * 4);
            #pragma unroll
            for (int i = 0; i < 4; i++) {
                int j = j0 + i * 64 + br;
                bvv[i] = (j < V) ? *(const float4*)(W2 + (size_t)j * H + k0 + bq * 4)
                                 : make_float4(0.f, 0.f, 0.f, 0.f);
            }
        }

        unsigned* AHc = (unsigned*)(bufc + K4_AH);
        unsigned* BHc = (unsigned*)(bufc + K4_BH);
        #pragma unroll
        for (int s = 0; s < 2; s++) {
            unsigned ah[2][4];
            #pragma unroll
            for (int mi = 0; mi < 2; mi++) {
                const unsigned* pa = AHc + (wm * 32 + mi * 16 + g) * K2P + s * 8 + t;
                ah[mi][0] = pa[0]; ah[mi][1] = pa[8 * K2P];
                ah[mi][2] = pa[4]; ah[mi][3] = pa[8 * K2P + 4];
            }
            #pragma unroll
            for (int ni = 0; ni < 8; ni++) {
                const unsigned* pb = BHc + (wn * 64 + ni * 8 + g) * K2P + s * 8 + t;
                unsigned bh0 = pb[0], bh1 = pb[4];
                #pragma unroll
                for (int mi = 0; mi < 2; mi++)
                    mma16(c[mi][ni], ah[mi], bh0, bh1);
            }
        }

        if (kt < 7) {
            char* bufn = smem + ((kt + 1) & 1) * K4_BUF;
            unsigned* AHn = (unsigned*)(bufn + K4_AH);
            unsigned* BHn = (unsigned*)(bufn + K4_BH);
            #pragma unroll
            for (int i = 0; i < 2; i++)
                *(uint2*)(AHn + (i * 64 + ar) * K2P + aq * 2) =
                    make_uint2(packhi(avv[i].x, avv[i].y), packhi(avv[i].z, avv[i].w));
            #pragma unroll
            for (int i = 0; i < 4; i++)
                *(uint2*)(BHn + (i * 64 + br) * K2P + bq * 2) =
                    make_uint2(packhi(bvv[i].x, bvv[i].y), packhi(bvv[i].z, bvv[i].w));
        }
        __syncthreads();
    }

    float* ssum = (float*)smem;
    #pragma unroll
    for (int mi = 0; mi < 2; mi++) {
        #pragma unroll
        for (int hf = 0; hf < 2; hf++) {
            const int r = wm * 32 + mi * 16 + hf * 8 + g;
            float ps = 0.f;
            #pragma unroll
            for (int ni = 0; ni < 8; ni++) {
                const int j = j0 + wn * 64 + ni * 8 + t * 2;
                if (j < V) {
                    float e0 = fexp(c[mi][ni][hf * 2 + 0] + b2[j]);
                    float e1 = fexp(c[mi][ni][hf * 2 + 1] + b2[j + 1]);
                    *(float2*)(g_logits + (size_t)r * V + j) = make_float2(e0, e1);
                    ps += e0 + e1;
                }
            }
            ps += __shfl_xor_sync(0xffffffffu, ps, 1);
            ps += __shfl_xor_sync(0xffffffffu, ps, 2);
            if (t == 0) ssum[r * 4 + wn] = ps;
        }
    }
    __syncthreads();
    if (tid < 128) {
        float s2 = ssum[tid * 4] + ssum[tid * 4 + 1] + ssum[tid * 4 + 2] + ssum[tid * 4 + 3];
        atomicAdd(&g_psum[tid], s2);
    }
}

// ---------------------------------------------------------------------------
__global__ void k5b_final(float* __restrict__ out)
{
    const int i = blockIdx.x * 256 + threadIdx.x;
    if (i >= B * VO) return;
    const int b = i / VO;
    const int c = i - b * VO;
    float v = 0.f;
    if (c < V) {
        const float gp = out[OFF_GP + b];
        v = g_logits[(size_t)b * V + c] * (1.f / g_psum[b]) * gp;
    }
    out[i] = v;
}

__global__ void k5c_scatter(const int* __restrict__ ewo, float* __restrict__ out)
{
    const int i = blockIdx.x * 256 + threadIdx.x;
    if (i >= B * S) return;
    const int b = i / S;
    const float gp = out[OFF_GP + b];
    const float a = out[OFF_AT + i];
    atomicAdd(out + (size_t)b * VO + ewo[i], a * (1.f - gp));
}

// ---------------------------------------------------------------------------
extern "C" void kernel_launch(void* const* d_in, const int* in_sizes, int n_in,
                              void* d_out, int out_size)
{
    const int*   idx      = (const int*)  d_in[0];
    const float* h0       = (const float*)d_in[1];
    const float* c0       = (const float*)d_in[2];
    const float* EO       = (const float*)d_in[3];
    const int*   emask    = (const int*)  d_in[4];
    const float* ctxv     = (const float*)d_in[5];
    const int*   ewo      = (const int*)  d_in[7];
    const float* coverage = (const float*)d_in[8];
    const float* emb      = (const float*)d_in[9];
    const float* Wi       = (const float*)d_in[10];
    const float* bi       = (const float*)d_in[11];
    const float* W_ih     = (const float*)d_in[12];
    const float* W_hh     = (const float*)d_in[13];
    const float* b_ih     = (const float*)d_in[14];
    const float* b_hh     = (const float*)d_in[15];
    const float* att_wh   = (const float*)d_in[16];
    const float* att_ws   = (const float*)d_in[17];
    const float* att_wc   = (const float*)d_in[18];
    const float* att_bc   = (const float*)d_in[19];
    const float* att_v    = (const float*)d_in[20];
    const float* gp_wh    = (const float*)d_in[21];
    const float* gp_bh    = (const float*)d_in[22];
    const float* gp_ws    = (const float*)d_in[23];
    const float* gp_bs    = (const float*)d_in[24];
    const float* gp_wx    = (const float*)d_in[25];
    const float* gp_bx    = (const float*)d_in[26];
    const float* out_w1   = (const float*)d_in[27];
    const float* out_b1   = (const float*)d_in[28];
    const float* out_w2   = (const float*)d_in[29];
    const float* out_b2   = (const float*)d_in[30];
    float* out = (float*)d_out;

    static int attr_done = 0;
    if (!attr_done) {
        cudaFuncSetAttribute(k2_mma, cudaFuncAttributeMaxDynamicSharedMemorySize, K2_SMEM);
        cudaFuncSetAttribute(k4_mma, cudaFuncAttributeMaxDynamicSharedMemorySize, K4_SMEM);
        attr_done = 1;
    }

    k0_wh<<<512, 256>>>(att_wh);
    {
        dim3 ga(2, 2);
        k1a_x<<<ga, 256>>>(idx, ctxv, emb, Wi, bi);
        dim3 gb(16, 2);
        k1b_gates<<<gb, 256>>>(h0, W_ih, W_hh, b_ih, b_hh);
        k1b2_lstm<<<B, 256>>>(c0, out, gp_ws, gp_bs, gp_wx, gp_bx, gp_bh);
        dim3 gc(8, 2);
        k1c_decbase<<<gc, 256>>>(att_ws, att_bc);
    }
    {
        dim3 g2((B * S) / 64, 2);
        k2_mma<<<g2, 256, K2_SMEM>>>(EO, att_wc, att_v, coverage);
    }
    k3a_softmax<<<B, 512>>>(coverage, emask, out);
    k3c_ctxpart<<<B * 16, 512>>>(EO, out);
    k3d_ctx<<<B, 512>>>(gp_wh, out);
    {
        dim3 g3b(4, 2);
        k3b_hidden<<<g3b, 256>>>(out_w1, out_b1, out);
    }
    k4_mma<<<(V + 255) / 256, 512, K4_SMEM>>>(out_w2, out_b2);
    k5b_final<<<(B * VO + 255) / 256, 256>>>(out);
    k5c_scatter<<<(B * S + 255) / 256, 256>>>(ewo, out);
}